// round 16
// baseline (speedup 1.0000x reference)
#include <cuda_runtime.h>
#include <cuda_fp16.h>
#include <stdint.h>
#include <math.h>

#define B_ 2
#define T_ 2048
#define C_ 1024
#define NH_ 16
#define HS_ 64
#define BD_ 16
#define DELTA_ 32
#define NDV 1280

// ---------------- scratch ----------------
__device__ float g_dispval[B_*T_*NDV];
__device__ float g_PWT  [B_*NH_*BD_*T_];
__device__ float g_PDT  [B_*NH_*BD_*T_];
__device__ float g_CW   [B_*T_*NH_*BD_];
__device__ __half g_xh [B_*T_*C_];
__device__ __half g_ah [B_*T_*C_];
__device__ __half g_wt [NDV*C_];         // disp|val W^T
__device__ __half g_wt2[C_*C_];          // cproj W^T

// ---------------- helpers ----------------
__device__ __forceinline__ uint32_t smem_u32(const void* p) {
    uint32_t a;
    asm("{ .reg .u64 t; cvta.to.shared.u64 t, %1; cvt.u32.u64 %0, t; }" : "=r"(a) : "l"(p));
    return a;
}
__device__ __forceinline__ void ldsm_x4(uint32_t* r, uint32_t addr) {
    asm volatile("ldmatrix.sync.aligned.m8n8.x4.shared.b16 {%0,%1,%2,%3}, [%4];"
                 : "=r"(r[0]), "=r"(r[1]), "=r"(r[2]), "=r"(r[3]) : "r"(addr));
}
__device__ __forceinline__ void mma16816h(float* c, const uint32_t* a, const uint32_t* b) {
    asm volatile("mma.sync.aligned.m16n8k16.row.col.f32.f16.f16.f32 "
                 "{%0,%1,%2,%3}, {%4,%5,%6,%7}, {%8,%9}, {%0,%1,%2,%3};"
                 : "+f"(c[0]), "+f"(c[1]), "+f"(c[2]), "+f"(c[3])
                 : "r"(a[0]), "r"(a[1]), "r"(a[2]), "r"(a[3]), "r"(b[0]), "r"(b[1]));
}
__device__ __forceinline__ float tanh_fast(float x) {
    float y; asm("tanh.approx.f32 %0, %1;" : "=f"(y) : "f"(x)); return y;
}
__device__ __forceinline__ float gelu_fast(float x) {
    float t = tanh_fast(0.7978845608028654f * (x + 0.044715f * x * x * x));
    return 0.5f * x * (1.f + t);
}

// ---------------------------------------------------------------------------
// x (fp32) -> fp16
// ---------------------------------------------------------------------------
__global__ void cvt_fp16(const float4* __restrict__ in,
                         __half2* __restrict__ out, int n4)
{
    int i = blockIdx.x * blockDim.x + threadIdx.x;
    int stride = gridDim.x * blockDim.x;
    for (; i < n4; i += stride) {
        float4 v = in[i];
        out[i*2+0] = __floats2half2_rn(v.x, v.y);
        out[i*2+1] = __floats2half2_rn(v.z, v.w);
    }
}

// ---------------------------------------------------------------------------
// Batched transpose of all three weights -> fp16, single launch.
// tiles: disp 8x32=256, val 32x32=1024, cproj 1024. linear block index.
// ---------------------------------------------------------------------------
__global__ void transpose_all(const float* __restrict__ w_disp,
                              const float* __restrict__ w_val,
                              const float* __restrict__ w_cproj,
                              __half* __restrict__ Th, __half* __restrict__ Th2)
{
    __shared__ float tile[32][33];
    int bid = blockIdx.x;
    const float* W; __half* Tdst; int N, roff, bx, by;
    if (bid < 256)       { W = w_disp;  Tdst = Th;  N = 256;  roff = 0;
                           bx = bid & 7;          by = bid >> 3; }
    else if (bid < 1280) { int r = bid - 256; W = w_val; Tdst = Th; N = C_; roff = 256;
                           bx = r & 31;           by = r >> 5; }
    else                 { int r = bid - 1280; W = w_cproj; Tdst = Th2; N = C_; roff = 0;
                           bx = r & 31;           by = r >> 5; }
    int tx = threadIdx.x, ty = threadIdx.y;
    #pragma unroll
    for (int i = ty; i < 32; i += 8)
        tile[i][tx] = W[(size_t)(by*32 + i) * N + bx*32 + tx];
    __syncthreads();
    #pragma unroll
    for (int i = ty; i < 32; i += 8) {
        size_t o = (size_t)(roff + bx*32 + i) * C_ + by*32 + tx;
        Tdst[o] = __float2half(tile[tx][i]);
    }
}

// ---------------------------------------------------------------------------
// fp16 GEMM: CTA 128x128, BK=64, 3-stage cp.async ring, 256 threads.
// ---------------------------------------------------------------------------
#define PITCHB 144
#define TILEB (128*PITCHB)
#define STAGEB (2*TILEB)
#define NSTG 3
#define GEMM_SMEM (NSTG*STAGEB)          // 110592

__global__ __launch_bounds__(256, 2) void gemm_fp16(
    const __half* __restrict__ Ah, const __half* __restrict__ BT,
    const float* __restrict__ bias1, const float* __restrict__ bias2, int nsplit,
    float* __restrict__ Cout, int M, int N, int K)
{
    extern __shared__ char smraw[];
    uint32_t sbase = smem_u32(smraw);

    int tid = threadIdx.x, lane = tid & 31, wid = tid >> 5;
    int wm = wid >> 2, wn = wid & 3;
    int m0 = blockIdx.y * 128, n0 = blockIdx.x * 128;

    const __half* gA = Ah + (size_t)m0 * K;
    const __half* gB = BT + (size_t)n0 * K;

    float acc[4][4][4];
    #pragma unroll
    for (int i = 0; i < 4; i++)
        #pragma unroll
        for (int j = 0; j < 4; j++)
            #pragma unroll
            for (int q = 0; q < 4; q++) acc[i][j][q] = 0.f;

    auto load_stage = [&](int slot, int ks) {
        uint32_t base = sbase + slot * STAGEB;
        #pragma unroll
        for (int it = 0; it < 8; it++) {
            int idx = it * 256 + tid;
            int tile = idx >> 10, rem = idx & 1023;
            int row = rem >> 3, j = rem & 7;
            uint32_t sa = base + tile * TILEB + row * PITCHB + j * 16;
            const __half* g = (tile ? gB : gA) + (size_t)row * K + ks + j * 8;
            asm volatile("cp.async.cg.shared.global [%0], [%1], 16;" :: "r"(sa), "l"(g));
        }
        asm volatile("cp.async.commit_group;");
    };

    const int nch = K / 64;
    load_stage(0, 0);
    load_stage(1, 64);

    int arow = (lane & 7) + ((lane >> 3) & 1) * 8;
    int acolo = (lane >> 4) * 8;
    int brow = (lane & 7) + (lane >> 4) * 8;
    int bcolo = ((lane >> 3) & 1) * 8;

    int slot = 0, nslot = 2;
    for (int s = 0; s < nch; s++) {
        if (s + 1 < nch) {
            asm volatile("cp.async.wait_group 1;");
        } else {
            asm volatile("cp.async.wait_group 0;");
        }
        __syncthreads();

        uint32_t base = sbase + slot * STAGEB;
        uint32_t aB = base, bB = base + TILEB;

        #pragma unroll
        for (int h = 0; h < 4; h++) {
            int k0 = h * 16;
            uint32_t bh[4][2];
            #pragma unroll
            for (int p = 0; p < 2; p++) {
                uint32_t off = (uint32_t)((wn*32 + p*16 + brow) * PITCHB + (k0 + bcolo) * 2);
                uint32_t t[4];
                ldsm_x4(t, bB + off);
                bh[2*p][0]=t[0]; bh[2*p][1]=t[1]; bh[2*p+1][0]=t[2]; bh[2*p+1][1]=t[3];
            }
            uint32_t ah[4][4];
            #pragma unroll
            for (int mi = 0; mi < 4; mi++) {
                uint32_t off = (uint32_t)((wm*64 + mi*16 + arow) * PITCHB + (k0 + acolo) * 2);
                ldsm_x4(ah[mi], aB + off);
            }
            #pragma unroll
            for (int mi = 0; mi < 4; mi++)
                #pragma unroll
                for (int ni = 0; ni < 4; ni++)
                    mma16816h(acc[mi][ni], ah[mi], bh[ni]);
        }

        if (s + 2 < nch) {
            load_stage(nslot, (s + 2) * 64);
            nslot = (nslot + 1 == NSTG) ? 0 : nslot + 1;
        }
        slot = (slot + 1 == NSTG) ? 0 : slot + 1;
    }

    int crow = lane >> 2, ccol = (lane & 3) * 2;
    #pragma unroll
    for (int mi = 0; mi < 4; mi++) {
        int r = m0 + wm*64 + mi*16 + crow;
        #pragma unroll
        for (int ni = 0; ni < 4; ni++) {
            int c = n0 + wn*32 + ni*8 + ccol;
            float b0 = (c   < nsplit) ? bias1[c]   : bias2[c   - nsplit];
            float b1 = (c+1 < nsplit) ? bias1[c+1] : bias2[c+1 - nsplit];
            float2 v0 = { acc[mi][ni][0] + b0, acc[mi][ni][1] + b1 };
            float2 v1 = { acc[mi][ni][2] + b0, acc[mi][ni][3] + b1 };
            *(float2*)(Cout + (size_t)r * N + c)       = v0;
            *(float2*)(Cout + (size_t)(r+8) * N + c)   = v1;
        }
    }
}

// ---------------------------------------------------------------------------
// Pass A: per token; writes PWT/PDT transposed [b][n][k][t], CW token-major.
// ---------------------------------------------------------------------------
__global__ __launch_bounds__(256) void passA(
    const float* __restrict__ dispval,
    const float* __restrict__ w_state, const float* __restrict__ b_state,
    const float* __restrict__ w_strain, const float* __restrict__ b_strain,
    const float* __restrict__ w_state_i, const float* __restrict__ w_state_j,
    const float* __restrict__ w_damage,
    float* __restrict__ PWT, float* __restrict__ CW, float* __restrict__ PDT)
{
    __shared__ float wST[256], wS[256], wI[256], wJ[256], wD[256];
    __shared__ float bST[16], bS[16];
    __shared__ float sdisp[256], smean[256], sstate[256];
    int tid = threadIdx.x;
    wST[tid] = w_state[tid];
    wS[tid]  = w_strain[tid];
    wI[tid]  = w_state_i[tid];
    wJ[tid]  = w_state_j[tid];
    wD[tid]  = w_damage[tid];
    if (tid < 16) { bST[tid] = b_state[tid]; bS[tid] = b_strain[tid]; }
    __syncthreads();

    int g = blockIdx.x * 16 + (tid >> 4);
    int k = tid & 15;
    int n  = g & (NH_-1);
    int bt = g >> 4;
    int t  = bt & (T_-1);
    int b  = bt >> 11;

    int col = n * BD_ + k;
    float dt = dispval[(size_t)bt * NDV + col];
    sdisp[tid] = dt;
    const float* cp = dispval + (size_t)(b*T_) * NDV + col;
    int d0 = (t >= DELTA_-1) ? 0 : (DELTA_-1 - t);
    float s = 0.f;
    for (int dd = d0; dd < DELTA_; dd++)
        s += cp[(size_t)(t - (DELTA_-1) + dd) * NDV];
    float cnt = (float)(DELTA_ - d0);
    smean[tid] = s / cnt - dt;
    __syncwarp();

    int gb = tid & ~15;
    float st = bST[k];
    #pragma unroll
    for (int i = 0; i < 16; i++) st += smean[gb + i] * wST[i*16 + k];
    sstate[tid] = st;
    __syncwarp();

    float dW = 0.f, dD = 0.f, sI = 0.f, sJ = 0.f;
    #pragma unroll
    for (int i = 0; i < 16; i++) {
        float dv = sdisp[gb + i], sv = sstate[gb + i];
        dW += dv * wS[i*16 + k];
        dD += dv * wD[i*16 + k];
        sI += sv * wI[i*16 + k];
        sJ += sv * wJ[i*16 + k];
    }
    size_t oT = (((size_t)(b*NH_ + n))*BD_ + k)*T_ + t;
    PWT[oT] = dW + sJ;
    PDT[oT] = dD;
    CW[(size_t)g*BD_ + k] = -dW + sI + bS[k];
}

// ---------------------------------------------------------------------------
// Pass B: one warp per (b,t,n); relpos computed in-block; hoisted loads.
// ---------------------------------------------------------------------------
__global__ __launch_bounds__(256) void passB(
    const float* __restrict__ PWT, const float* __restrict__ CW,
    const float* __restrict__ PDT, const float* __restrict__ dispval,
    const float* __restrict__ rel_emb, const float* __restrict__ w_pos,
    const float* __restrict__ w_bond_out, const float* __restrict__ b_bond_out,
    const float* __restrict__ b_damage,
    const float* __restrict__ w_damage_out, const float* __restrict__ b_damage_out,
    __half* __restrict__ attn)
{
    __shared__ float srelT[512];                 // [j][d]
    __shared__ float sbo[16], sdo[16], sbd[16];
    __shared__ float sscal[2];
    int tid = threadIdx.x;
    // relpos: entry (j,d) = sum_i rel_emb[d*16+i] * w_pos[i*16+j]; 2 per thread
    {
        #pragma unroll
        for (int e = 0; e < 2; e++) {
            int idx = tid + e*256;
            int j = idx >> 5, d = idx & 31;
            float acc = 0.f;
            #pragma unroll
            for (int i = 0; i < 16; i++)
                acc += rel_emb[d*16 + i] * w_pos[i*16 + j];
            srelT[j*32 + d] = acc;
        }
    }
    if (tid < 16) { sbo[tid] = w_bond_out[tid]; sdo[tid] = w_damage_out[tid];
                    sbd[tid] = b_damage[tid]; }
    if (tid == 0) { sscal[0] = b_bond_out[0]; sscal[1] = b_damage_out[0]; }
    __syncthreads();

    int lane = tid & 31;
    int g = blockIdx.x * 8 + (tid >> 5);
    int n  = g & (NH_-1);
    int bt = g >> 4;
    int t  = bt & (T_-1);
    int b  = bt >> 11;

    int trow = t - (DELTA_-1) + lane;
    bool valid = trow >= 0;
    int trc = valid ? trow : 0;

    size_t planeT = ((size_t)(b*NH_ + n))*BD_*T_;
    size_t gc = (size_t)g*BD_;
    const float4* pCWt = (const float4*)(CW + gc);

    // hoist all window loads (48 LDGs in flight)
    float pwv[16], pdv[16], pdtj[16];
    #pragma unroll
    for (int j = 0; j < 16; j++) {
        size_t rowT = planeT + (size_t)j*T_;
        pwv[j]  = PWT[rowT + trc];
        pdv[j]  = PDT[rowT + trc];
        pdtj[j] = PDT[rowT + t];
    }

    float bond = sscal[0], dmgl = sscal[1];
    #pragma unroll
    for (int q = 0; q < 4; q++) {
        float4 cw = pCWt[q];
        float cwv[4] = {cw.x, cw.y, cw.z, cw.w};
        #pragma unroll
        for (int jj = 0; jj < 4; jj++) {
            int j = q*4 + jj;
            float aB = pwv[j] + cwv[jj] + srelT[j*32 + lane];
            float aD = pdv[j] + sbd[j] - pdtj[j];
            bond += gelu_fast(aB) * sbo[j];
            dmgl += gelu_fast(aD) * sdo[j];
        }
    }

    float damage = 0.5f + 0.5f * tanh_fast(0.5f * dmgl);
    float logit = valid ? (bond - 10.f * damage) : -INFINITY;

    float mx = logit;
    #pragma unroll
    for (int o = 16; o; o >>= 1) mx = fmaxf(mx, __shfl_xor_sync(0xffffffffu, mx, o));
    float e = valid ? __expf(logit - mx) : 0.f;
    float se = e;
    #pragma unroll
    for (int o = 16; o; o >>= 1) se += __shfl_xor_sync(0xffffffffu, se, o);
    float w = e / se;

    // full-unroll val loop: weight is 0 for invalid slots, clamp address only
    float a0 = 0.f, a1 = 0.f;
    const float2* vbase2 = (const float2*)(dispval + (size_t)(b*T_)*NDV + 256 + n*HS_);
    #pragma unroll
    for (int dd = 0; dd < DELTA_; dd++) {
        float wd = __shfl_sync(0xffffffffu, w, dd);
        int tg = t - (DELTA_-1) + dd;
        tg = tg < 0 ? 0 : tg;
        float2 v = vbase2[(size_t)tg * (NDV/2) + lane];
        a0 += wd * v.x;
        a1 += wd * v.y;
    }
    size_t ob = (size_t)bt*C_ + n*HS_;
    ((__half2*)(attn + ob))[lane] = __floats2half2_rn(a0, a1);
}

// ---------------------------------------------------------------------------
extern "C" void kernel_launch(void* const* d_in, const int* in_sizes, int n_in,
                              void* d_out, int out_size)
{
    (void)in_sizes; (void)n_in; (void)out_size;
    const float* x            = (const float*)d_in[0];
    const float* w_disp       = (const float*)d_in[1];
    const float* b_disp       = (const float*)d_in[2];
    const float* w_val        = (const float*)d_in[3];
    const float* b_val        = (const float*)d_in[4];
    const float* rel_pos_emb  = (const float*)d_in[5];
    const float* w_state      = (const float*)d_in[6];
    const float* b_state      = (const float*)d_in[7];
    const float* w_strain     = (const float*)d_in[8];
    const float* b_strain     = (const float*)d_in[9];
    const float* w_state_i    = (const float*)d_in[10];
    const float* w_state_j    = (const float*)d_in[11];
    const float* w_pos        = (const float*)d_in[12];
    const float* w_bond_out   = (const float*)d_in[13];
    const float* b_bond_out   = (const float*)d_in[14];
    const float* w_damage     = (const float*)d_in[15];
    const float* b_damage     = (const float*)d_in[16];
    const float* w_damage_out = (const float*)d_in[17];
    const float* b_damage_out = (const float*)d_in[18];
    const float* w_cproj      = (const float*)d_in[19];
    const float* b_cproj      = (const float*)d_in[20];
    float* out = (float*)d_out;

    float *p_dv, *p_PWT, *p_CW, *p_PDT;
    __half *p_xh, *p_ah, *p_wt, *p_wt2;
    cudaGetSymbolAddress((void**)&p_dv,    g_dispval);
    cudaGetSymbolAddress((void**)&p_PWT,   g_PWT);
    cudaGetSymbolAddress((void**)&p_CW,    g_CW);
    cudaGetSymbolAddress((void**)&p_PDT,   g_PDT);
    cudaGetSymbolAddress((void**)&p_xh,    g_xh);
    cudaGetSymbolAddress((void**)&p_ah,    g_ah);
    cudaGetSymbolAddress((void**)&p_wt,    g_wt);
    cudaGetSymbolAddress((void**)&p_wt2,   g_wt2);

    cudaFuncSetAttribute(gemm_fp16, cudaFuncAttributeMaxDynamicSharedMemorySize, GEMM_SMEM);

    const int M = B_ * T_;   // 4096

    // 1: x -> fp16
    cvt_fp16<<<1024, 256>>>((const float4*)x, (__half2*)p_xh, (M * C_) / 4);
    // 2: all weight transposes, single launch
    transpose_all<<<2304, dim3(32, 8)>>>(w_disp, w_val, w_cproj, p_wt, p_wt2);
    // 3: fused disp|val GEMM
    gemm_fp16<<<dim3(NDV/128, M/128), 256, GEMM_SMEM>>>(p_xh, p_wt,
                                                        b_disp, b_val, 256,
                                                        p_dv, M, NDV, C_);
    // 4: passA  (PROFILED slot)
    passA<<<(B_*T_*NH_)/16, 256>>>(p_dv, w_state, b_state, w_strain, b_strain,
                                   w_state_i, w_state_j, w_damage,
                                   p_PWT, p_CW, p_PDT);
    // 5: passB
    passB<<<(B_*T_*NH_)/8, 256>>>(p_PWT, p_CW, p_PDT, p_dv,
                                  rel_pos_emb, w_pos,
                                  w_bond_out, b_bond_out, b_damage,
                                  w_damage_out, b_damage_out, p_ah);
    // 6: out = attn @ w_cproj + b_cproj
    gemm_fp16<<<dim3(C_/128, M/128), 256, GEMM_SMEM>>>(p_ah, p_wt2,
                                                       b_cproj, b_cproj, 0,
                                                       out, M, C_, C_);
}

// round 17
// speedup vs baseline: 1.2678x; 1.2678x over previous
#include <cuda_runtime.h>
#include <cuda_fp16.h>
#include <stdint.h>
#include <math.h>

#define B_ 2
#define T_ 2048
#define C_ 1024
#define NH_ 16
#define HS_ 64
#define BD_ 16
#define DELTA_ 32
#define NDV 1280

// ---------------- scratch ----------------
__device__ float g_dispval[B_*T_*NDV];
__device__ float g_PWT  [B_*NH_*BD_*T_];
__device__ float g_PDT  [B_*NH_*BD_*T_];
__device__ float g_CW   [B_*T_*NH_*BD_];
__device__ float g_relpos[DELTA_*BD_];
__device__ __half g_xh [B_*T_*C_];
__device__ __half g_ah [B_*T_*C_];
__device__ __half g_wt [NDV*C_];
__device__ __half g_wt2[C_*C_];

// ---------------- helpers ----------------
__device__ __forceinline__ uint32_t smem_u32(const void* p) {
    uint32_t a;
    asm("{ .reg .u64 t; cvta.to.shared.u64 t, %1; cvt.u32.u64 %0, t; }" : "=r"(a) : "l"(p));
    return a;
}
__device__ __forceinline__ void ldsm_x4(uint32_t* r, uint32_t addr) {
    asm volatile("ldmatrix.sync.aligned.m8n8.x4.shared.b16 {%0,%1,%2,%3}, [%4];"
                 : "=r"(r[0]), "=r"(r[1]), "=r"(r[2]), "=r"(r[3]) : "r"(addr));
}
__device__ __forceinline__ void mma16816h(float* c, const uint32_t* a, const uint32_t* b) {
    asm volatile("mma.sync.aligned.m16n8k16.row.col.f32.f16.f16.f32 "
                 "{%0,%1,%2,%3}, {%4,%5,%6,%7}, {%8,%9}, {%0,%1,%2,%3};"
                 : "+f"(c[0]), "+f"(c[1]), "+f"(c[2]), "+f"(c[3])
                 : "r"(a[0]), "r"(a[1]), "r"(a[2]), "r"(a[3]), "r"(b[0]), "r"(b[1]));
}
__device__ __forceinline__ float tanh_fast(float x) {
    float y; asm("tanh.approx.f32 %0, %1;" : "=f"(y) : "f"(x)); return y;
}
__device__ __forceinline__ float gelu_fast(float x) {
    float t = tanh_fast(0.7978845608028654f * (x + 0.044715f * x * x * x));
    return 0.5f * x * (1.f + t);
}

// ---------------------------------------------------------------------------
// x (fp32) -> fp16
// ---------------------------------------------------------------------------
__global__ void cvt_fp16(const float4* __restrict__ in,
                         __half2* __restrict__ out, int n4)
{
    int i = blockIdx.x * blockDim.x + threadIdx.x;
    int stride = gridDim.x * blockDim.x;
    for (; i < n4; i += stride) {
        float4 v = in[i];
        out[i*2+0] = __floats2half2_rn(v.x, v.y);
        out[i*2+1] = __floats2half2_rn(v.z, v.w);
    }
}

// ---------------------------------------------------------------------------
// disp|val transposes fused into one launch (tiles: disp 256, val 1024)
// ---------------------------------------------------------------------------
__global__ void transpose_dv(const float* __restrict__ w_disp,
                             const float* __restrict__ w_val,
                             __half* __restrict__ Th)
{
    __shared__ float tile[32][33];
    int bid = blockIdx.x;
    const float* W; int N, roff, bx, by;
    if (bid < 256) { W = w_disp; N = 256; roff = 0;   bx = bid & 7;  by = bid >> 3; }
    else { int r = bid - 256; W = w_val; N = C_; roff = 256; bx = r & 31; by = r >> 5; }
    int tx = threadIdx.x, ty = threadIdx.y;
    #pragma unroll
    for (int i = ty; i < 32; i += 8)
        tile[i][tx] = W[(size_t)(by*32 + i) * N + bx*32 + tx];
    __syncthreads();
    #pragma unroll
    for (int i = ty; i < 32; i += 8) {
        size_t o = (size_t)(roff + bx*32 + i) * C_ + by*32 + tx;
        Th[o] = __float2half(tile[tx][i]);
    }
}

// ---------------------------------------------------------------------------
// single-weight transpose (for cproj)
// ---------------------------------------------------------------------------
__global__ void transpose_h(const float* __restrict__ W,
                            __half* __restrict__ Th, int K, int N, int roff)
{
    __shared__ float tile[32][33];
    int bx = blockIdx.x, by = blockIdx.y;
    int tx = threadIdx.x, ty = threadIdx.y;
    #pragma unroll
    for (int i = ty; i < 32; i += 8)
        tile[i][tx] = W[(size_t)(by*32 + i) * N + bx*32 + tx];
    __syncthreads();
    #pragma unroll
    for (int i = ty; i < 32; i += 8) {
        size_t o = (size_t)(roff + bx*32 + i) * K + by*32 + tx;
        Th[o] = __float2half(tile[tx][i]);
    }
}

// ---------------------------------------------------------------------------
// fp16 GEMM: CTA 128x128, BK=64, 3-stage cp.async ring, 256 threads.
// ---------------------------------------------------------------------------
#define PITCHB 144
#define TILEB (128*PITCHB)
#define STAGEB (2*TILEB)
#define NSTG 3
#define GEMM_SMEM (NSTG*STAGEB)

__global__ __launch_bounds__(256, 2) void gemm_fp16(
    const __half* __restrict__ Ah, const __half* __restrict__ BT,
    const float* __restrict__ bias1, const float* __restrict__ bias2, int nsplit,
    float* __restrict__ Cout, int M, int N, int K)
{
    extern __shared__ char smraw[];
    uint32_t sbase = smem_u32(smraw);

    int tid = threadIdx.x, lane = tid & 31, wid = tid >> 5;
    int wm = wid >> 2, wn = wid & 3;
    int m0 = blockIdx.y * 128, n0 = blockIdx.x * 128;

    const __half* gA = Ah + (size_t)m0 * K;
    const __half* gB = BT + (size_t)n0 * K;

    float acc[4][4][4];
    #pragma unroll
    for (int i = 0; i < 4; i++)
        #pragma unroll
        for (int j = 0; j < 4; j++)
            #pragma unroll
            for (int q = 0; q < 4; q++) acc[i][j][q] = 0.f;

    auto load_stage = [&](int slot, int ks) {
        uint32_t base = sbase + slot * STAGEB;
        #pragma unroll
        for (int it = 0; it < 8; it++) {
            int idx = it * 256 + tid;
            int tile = idx >> 10, rem = idx & 1023;
            int row = rem >> 3, j = rem & 7;
            uint32_t sa = base + tile * TILEB + row * PITCHB + j * 16;
            const __half* g = (tile ? gB : gA) + (size_t)row * K + ks + j * 8;
            asm volatile("cp.async.cg.shared.global [%0], [%1], 16;" :: "r"(sa), "l"(g));
        }
        asm volatile("cp.async.commit_group;");
    };

    const int nch = K / 64;
    load_stage(0, 0);
    load_stage(1, 64);

    int arow = (lane & 7) + ((lane >> 3) & 1) * 8;
    int acolo = (lane >> 4) * 8;
    int brow = (lane & 7) + (lane >> 4) * 8;
    int bcolo = ((lane >> 3) & 1) * 8;

    int slot = 0, nslot = 2;
    for (int s = 0; s < nch; s++) {
        if (s + 1 < nch) {
            asm volatile("cp.async.wait_group 1;");
        } else {
            asm volatile("cp.async.wait_group 0;");
        }
        __syncthreads();

        uint32_t base = sbase + slot * STAGEB;
        uint32_t aB = base, bB = base + TILEB;

        #pragma unroll
        for (int h = 0; h < 4; h++) {
            int k0 = h * 16;
            uint32_t bh[4][2];
            #pragma unroll
            for (int p = 0; p < 2; p++) {
                uint32_t off = (uint32_t)((wn*32 + p*16 + brow) * PITCHB + (k0 + bcolo) * 2);
                uint32_t t[4];
                ldsm_x4(t, bB + off);
                bh[2*p][0]=t[0]; bh[2*p][1]=t[1]; bh[2*p+1][0]=t[2]; bh[2*p+1][1]=t[3];
            }
            uint32_t ah[4][4];
            #pragma unroll
            for (int mi = 0; mi < 4; mi++) {
                uint32_t off = (uint32_t)((wm*64 + mi*16 + arow) * PITCHB + (k0 + acolo) * 2);
                ldsm_x4(ah[mi], aB + off);
            }
            #pragma unroll
            for (int mi = 0; mi < 4; mi++)
                #pragma unroll
                for (int ni = 0; ni < 4; ni++)
                    mma16816h(acc[mi][ni], ah[mi], bh[ni]);
        }

        if (s + 2 < nch) {
            load_stage(nslot, (s + 2) * 64);
            nslot = (nslot + 1 == NSTG) ? 0 : nslot + 1;
        }
        slot = (slot + 1 == NSTG) ? 0 : slot + 1;
    }

    int crow = lane >> 2, ccol = (lane & 3) * 2;
    #pragma unroll
    for (int mi = 0; mi < 4; mi++) {
        int r = m0 + wm*64 + mi*16 + crow;
        #pragma unroll
        for (int ni = 0; ni < 4; ni++) {
            int c = n0 + wn*32 + ni*8 + ccol;
            float b0 = (c   < nsplit) ? bias1[c]   : bias2[c   - nsplit];
            float b1 = (c+1 < nsplit) ? bias1[c+1] : bias2[c+1 - nsplit];
            float2 v0 = { acc[mi][ni][0] + b0, acc[mi][ni][1] + b1 };
            float2 v1 = { acc[mi][ni][2] + b0, acc[mi][ni][3] + b1 };
            *(float2*)(Cout + (size_t)r * N + c)       = v0;
            *(float2*)(Cout + (size_t)(r+8) * N + c)   = v1;
        }
    }
}

// ---------------------------------------------------------------------------
// relpos[d][j] = rel_emb[:32] @ w_pos
// ---------------------------------------------------------------------------
__global__ void relpos_k(const float* __restrict__ rel_emb,
                         const float* __restrict__ w_pos)
{
    int tid = threadIdx.x;
    int dd = tid >> 4, j = tid & 15;
    float acc = 0.f;
    #pragma unroll
    for (int i = 0; i < 16; i++) acc += rel_emb[dd*16 + i] * w_pos[i*16 + j];
    g_relpos[tid] = acc;
}

// ---------------------------------------------------------------------------
// Pass A (sliding-window): block = (b, 16-token tile), thread owns column
// c=(n,k). Running window sum -> 8x less L1 traffic than per-token re-read.
// ---------------------------------------------------------------------------
#define TTA 16

__global__ __launch_bounds__(256) void passA(
    const float* __restrict__ dispval,
    const float* __restrict__ w_state, const float* __restrict__ b_state,
    const float* __restrict__ w_strain, const float* __restrict__ b_strain,
    const float* __restrict__ w_state_i, const float* __restrict__ w_state_j,
    const float* __restrict__ w_damage,
    float* __restrict__ PWT, float* __restrict__ CW, float* __restrict__ PDT)
{
    __shared__ float wST[256], wS[256], wI[256], wJ[256], wD[256];
    __shared__ float bST[16], bS[16];
    __shared__ float sdisp[256], smean[256], sstate[256];
    int tid = threadIdx.x;
    wST[tid] = w_state[tid];
    wS[tid]  = w_strain[tid];
    wI[tid]  = w_state_i[tid];
    wJ[tid]  = w_state_j[tid];
    wD[tid]  = w_damage[tid];
    if (tid < 16) { bST[tid] = b_state[tid]; bS[tid] = b_strain[tid]; }
    __syncthreads();

    int bidx = blockIdx.x;
    int tt = bidx & (T_/TTA - 1);          // 0..127
    int b  = bidx >> 7;
    int t0 = tt * TTA;
    int n = tid >> 4, k = tid & 15;
    int gb = tid & ~15;

    const float* dcol = dispval + (size_t)(b*T_)*NDV + tid;   // column tid

    // init S over rows [max(0, t0-31), t0-1]
    float S = 0.f;
    int lo = t0 - (DELTA_-1); if (lo < 0) lo = 0;
    for (int r = lo; r < t0; r++) S += dcol[(size_t)r * NDV];

    for (int t = t0; t < t0 + TTA; t++) {
        float dt = dcol[(size_t)t * NDV];
        S += dt;
        if (t != t0 && t >= DELTA_) S -= dcol[(size_t)(t - DELTA_) * NDV];
        float cnt = (float)(t + 1 < DELTA_ ? t + 1 : DELTA_);
        sdisp[tid] = dt;
        smean[tid] = S / cnt - dt;
        __syncwarp();

        float st = bST[k];
        #pragma unroll
        for (int i = 0; i < 16; i++) st += smean[gb + i] * wST[i*16 + k];
        sstate[tid] = st;
        __syncwarp();

        float dW = 0.f, dD = 0.f, sI = 0.f, sJ = 0.f;
        #pragma unroll
        for (int i = 0; i < 16; i++) {
            float dv = sdisp[gb + i], sv = sstate[gb + i];
            dW += dv * wS[i*16 + k];
            dD += dv * wD[i*16 + k];
            sI += sv * wI[i*16 + k];
            sJ += sv * wJ[i*16 + k];
        }
        size_t oT = (((size_t)(b*NH_ + n))*BD_ + k)*T_ + t;
        PWT[oT] = dW + sJ;
        PDT[oT] = dD;
        CW[(((size_t)(b*T_ + t))*NH_ + n)*BD_ + k] = -dW + sI + bS[k];
        __syncwarp();
    }
}

// ---------------------------------------------------------------------------
// Pass B (R15 form): one warp per (b,t,n); coalesced window reads.
// ---------------------------------------------------------------------------
__global__ __launch_bounds__(256) void passB(
    const float* __restrict__ PWT, const float* __restrict__ CW,
    const float* __restrict__ PDT, const float* __restrict__ dispval,
    const float* __restrict__ w_bond_out, const float* __restrict__ b_bond_out,
    const float* __restrict__ b_damage,
    const float* __restrict__ w_damage_out, const float* __restrict__ b_damage_out,
    __half* __restrict__ attn)
{
    __shared__ float srelT[512];                 // [j][d]
    __shared__ float sbo[16], sdo[16], sbd[16];
    __shared__ float sscal[2];
    int tid = threadIdx.x;
    {
        int d1 = tid >> 4, j1 = tid & 15;
        srelT[j1*32 + d1] = g_relpos[tid];
        int t2 = tid + 256;
        int d2 = t2 >> 4, j2 = t2 & 15;
        srelT[j2*32 + d2] = g_relpos[t2];
    }
    if (tid < 16) { sbo[tid] = w_bond_out[tid]; sdo[tid] = w_damage_out[tid];
                    sbd[tid] = b_damage[tid]; }
    if (tid == 0) { sscal[0] = b_bond_out[0]; sscal[1] = b_damage_out[0]; }
    __syncthreads();

    int lane = tid & 31;
    int g = blockIdx.x * 8 + (tid >> 5);
    int n  = g & (NH_-1);
    int bt = g >> 4;
    int t  = bt & (T_-1);
    int b  = bt >> 11;

    int trow = t - (DELTA_-1) + lane;
    bool valid = trow >= 0;
    int trc = valid ? trow : 0;

    size_t planeT = ((size_t)(b*NH_ + n))*BD_*T_;
    size_t gc = (size_t)g*BD_;
    const float4* pCWt = (const float4*)(CW + gc);

    float bond = sscal[0], dmgl = sscal[1];
    #pragma unroll
    for (int q = 0; q < 4; q++) {
        float4 cw = pCWt[q];
        float cwv[4] = {cw.x, cw.y, cw.z, cw.w};
        #pragma unroll
        for (int jj = 0; jj < 4; jj++) {
            int j = q*4 + jj;
            size_t rowT = planeT + (size_t)j*T_;
            float pwv  = PWT[rowT + trc];
            float pdv  = PDT[rowT + trc];
            float pdtj = PDT[rowT + t];
            float aB = pwv + cwv[jj] + srelT[j*32 + lane];
            float aD = pdv + sbd[j] - pdtj;
            bond += gelu_fast(aB) * sbo[j];
            dmgl += gelu_fast(aD) * sdo[j];
        }
    }

    float damage = 0.5f + 0.5f * tanh_fast(0.5f * dmgl);
    float logit = valid ? (bond - 10.f * damage) : -INFINITY;

    float mx = logit;
    #pragma unroll
    for (int o = 16; o; o >>= 1) mx = fmaxf(mx, __shfl_xor_sync(0xffffffffu, mx, o));
    float e = valid ? __expf(logit - mx) : 0.f;
    float se = e;
    #pragma unroll
    for (int o = 16; o; o >>= 1) se += __shfl_xor_sync(0xffffffffu, se, o);
    float w = e / se;

    float a0 = 0.f, a1 = 0.f;
    int d0 = (t >= DELTA_-1) ? 0 : (DELTA_-1 - t);
    const float2* vbase2 = (const float2*)(dispval + (size_t)(b*T_)*NDV + 256 + n*HS_);
    for (int dd = d0; dd < DELTA_; dd++) {
        float wd = __shfl_sync(0xffffffffu, w, dd);
        float2 v = vbase2[(size_t)(t - (DELTA_-1) + dd) * (NDV/2) + lane];
        a0 += wd * v.x;
        a1 += wd * v.y;
    }
    size_t ob = (size_t)bt*C_ + n*HS_;
    ((__half2*)(attn + ob))[lane] = __floats2half2_rn(a0, a1);
}

// ---------------------------------------------------------------------------
extern "C" void kernel_launch(void* const* d_in, const int* in_sizes, int n_in,
                              void* d_out, int out_size)
{
    (void)in_sizes; (void)n_in; (void)out_size;
    const float* x            = (const float*)d_in[0];
    const float* w_disp       = (const float*)d_in[1];
    const float* b_disp       = (const float*)d_in[2];
    const float* w_val        = (const float*)d_in[3];
    const float* b_val        = (const float*)d_in[4];
    const float* rel_pos_emb  = (const float*)d_in[5];
    const float* w_state      = (const float*)d_in[6];
    const float* b_state      = (const float*)d_in[7];
    const float* w_strain     = (const float*)d_in[8];
    const float* b_strain     = (const float*)d_in[9];
    const float* w_state_i    = (const float*)d_in[10];
    const float* w_state_j    = (const float*)d_in[11];
    const float* w_pos        = (const float*)d_in[12];
    const float* w_bond_out   = (const float*)d_in[13];
    const float* b_bond_out   = (const float*)d_in[14];
    const float* w_damage     = (const float*)d_in[15];
    const float* b_damage     = (const float*)d_in[16];
    const float* w_damage_out = (const float*)d_in[17];
    const float* b_damage_out = (const float*)d_in[18];
    const float* w_cproj      = (const float*)d_in[19];
    const float* b_cproj      = (const float*)d_in[20];
    float* out = (float*)d_out;

    float *p_dv, *p_PWT, *p_CW, *p_PDT;
    __half *p_xh, *p_ah, *p_wt, *p_wt2;
    cudaGetSymbolAddress((void**)&p_dv,    g_dispval);
    cudaGetSymbolAddress((void**)&p_PWT,   g_PWT);
    cudaGetSymbolAddress((void**)&p_CW,    g_CW);
    cudaGetSymbolAddress((void**)&p_PDT,   g_PDT);
    cudaGetSymbolAddress((void**)&p_xh,    g_xh);
    cudaGetSymbolAddress((void**)&p_ah,    g_ah);
    cudaGetSymbolAddress((void**)&p_wt,    g_wt);
    cudaGetSymbolAddress((void**)&p_wt2,   g_wt2);

    cudaFuncSetAttribute(gemm_fp16, cudaFuncAttributeMaxDynamicSharedMemorySize, GEMM_SMEM);

    const int M = B_ * T_;   // 4096

    // 1: x -> fp16
    cvt_fp16<<<1024, 256>>>((const float4*)x, (__half2*)p_xh, (M * C_) / 4);
    // 2: disp|val W^T (fused single launch)
    transpose_dv<<<1280, dim3(32, 8)>>>(w_disp, w_val, p_wt);
    // 3: fused disp|val GEMM
    gemm_fp16<<<dim3(NDV/128, M/128), 256, GEMM_SMEM>>>(p_xh, p_wt,
                                                        b_disp, b_val, 256,
                                                        p_dv, M, NDV, C_);
    // 4: passA (sliding window)  -- PROFILED slot
    passA<<<B_*(T_/TTA), 256>>>(p_dv, w_state, b_state, w_strain, b_strain,
                                w_state_i, w_state_j, w_damage,
                                p_PWT, p_CW, p_PDT);
    // 5: relpos
    relpos_k<<<1, DELTA_*BD_>>>(rel_pos_emb, w_pos);
    // 6: passB
    passB<<<(B_*T_*NH_)/8, 256>>>(p_PWT, p_CW, p_PDT, p_dv,
                                  w_bond_out, b_bond_out, b_damage,
                                  w_damage_out, b_damage_out, p_ah);
    // 7: cproj W^T
    transpose_h<<<dim3(C_/32, C_/32), dim3(32, 8)>>>(w_cproj, p_wt2, C_, C_, 0);
    // 8: out = attn @ w_cproj + b_cproj
    gemm_fp16<<<dim3(C_/128, M/128), 256, GEMM_SMEM>>>(p_ah, p_wt2,
                                                       b_cproj, b_cproj, 0,
                                                       out, M, C_, C_);
}